// round 8
// baseline (speedup 1.0000x reference)
#include <cuda_runtime.h>
#include <math.h>

#define Bb   8
#define Cc   64
#define Nn   2048
#define KNB  32
#define NHEADS 8
#define EPSBN 1e-5f
#define NSLOPE 0.2f

// ---------------- scratch (device globals; no runtime allocation) ----------------
__device__ float g_xx[Bb * Nn];
__device__ float g_D[(size_t)Bb * Nn * Nn];             // 128 MB distance matrix
__device__ int   g_idx[Bb * Nn * KNB];
__device__ float g_Qt[(size_t)Bb * Nn * Cc];            // (B,N,64) point-major
__device__ float g_Kt[(size_t)Bb * Nn * Cc];
__device__ float g_Vt[(size_t)Bb * Nn * Cc];
__device__ float g_y [(size_t)Bb * Cc * Nn];
__device__ float g_y2[(size_t)Bb * Cc * Nn];
__device__ float g_mu1[Cc], g_rs1[Cc], g_mu2[Cc], g_rs2[Cc];
__device__ double g_ps [2][Cc][Bb];
__device__ double g_ps2[2][Cc][Bb];

// ---------------- packed f32x2 helpers (sm_103a FFMA2 path) ----------------
__device__ __forceinline__ unsigned long long pack2(float x, float y) {
    unsigned long long r;
    asm("mov.b64 %0, {%1, %2};" : "=l"(r) : "f"(x), "f"(y));
    return r;
}
__device__ __forceinline__ unsigned long long ffma2(unsigned long long a,
                                                    unsigned long long b,
                                                    unsigned long long c) {
    unsigned long long d;
    asm("fma.rn.f32x2 %0, %1, %2, %3;" : "=l"(d) : "l"(a), "l"(b), "l"(c));
    return d;
}
__device__ __forceinline__ void unpack2(unsigned long long v, float& lo, float& hi) {
    asm("mov.b64 {%0, %1}, %2;" : "=f"(lo), "=f"(hi) : "l"(v));
}

// ---------------- 1. squared norms ----------------
__global__ void xx_kernel(const float* __restrict__ x) {
    int i = blockIdx.x * blockDim.x + threadIdx.x;
    int b = i >> 11, n = i & (Nn - 1);
    const float* xp = x + (size_t)b * Cc * Nn + n;
    float s = 0.f;
#pragma unroll
    for (int c = 0; c < Cc; c++) { float v = xp[c * Nn]; s = fmaf(v, v, s); }
    g_xx[i] = s;
}

// ---------------- 2. neg squared distance matrix: symmetric upper-tri block pairs,
// packed f32x2 FMA inner loop ----------------
__global__ void __launch_bounds__(256, 2) dist_kernel(const float* __restrict__ x, int bpair) {
    int b = bpair * 2 + blockIdx.y;
    // map blockIdx.x (0..135) -> (bi, bj) with bi <= bj over 16x16 tile grid
    int p = blockIdx.x, bi = 0;
    while (p >= 16 - bi) { p -= 16 - bi; bi++; }
    int bj = bi + p;
    int i0 = bi * 128, j0 = bj * 128;

    __shared__ float As[32][132];
    __shared__ float Bs[32][132];
    int t = threadIdx.x;
    int tx = t & 15, ty = t >> 4;                 // 16 x 16 threads, 8x8 tile each
    const float* xb = x + (size_t)b * Cc * Nn;

    unsigned long long acc2[4][8];                // acc pairs along ii
#pragma unroll
    for (int ip = 0; ip < 4; ip++)
#pragma unroll
        for (int j = 0; j < 8; j++) acc2[ip][j] = 0ull;

    for (int kc = 0; kc < Cc; kc += 32) {
        __syncthreads();
        for (int idx = t; idx < 32 * 128; idx += 256) {
            int c = idx >> 7, q = idx & 127;
            As[c][q] = xb[(kc + c) * Nn + i0 + q];
            Bs[c][q] = xb[(kc + c) * Nn + j0 + q];
        }
        __syncthreads();
#pragma unroll
        for (int c = 0; c < 32; c++) {
            ulonglong2 ap0 = *(const ulonglong2*)&As[c][ty * 8];       // (a0,a1),(a2,a3)
            ulonglong2 ap1 = *(const ulonglong2*)&As[c][ty * 8 + 4];   // (a4,a5),(a6,a7)
            unsigned long long ap[4] = {ap0.x, ap0.y, ap1.x, ap1.y};
            float4 b0 = *(const float4*)&Bs[c][tx * 8];
            float4 b1 = *(const float4*)&Bs[c][tx * 8 + 4];
            float bv[8] = {b0.x, b0.y, b0.z, b0.w, b1.x, b1.y, b1.z, b1.w};
            unsigned long long bc[8];
#pragma unroll
            for (int j = 0; j < 8; j++) bc[j] = pack2(bv[j], bv[j]);
#pragma unroll
            for (int ip = 0; ip < 4; ip++)
#pragma unroll
                for (int j = 0; j < 8; j++)
                    acc2[ip][j] = ffma2(ap[ip], bc[j], acc2[ip][j]);
        }
    }

    float acc[8][8];
#pragma unroll
    for (int ip = 0; ip < 4; ip++)
#pragma unroll
        for (int j = 0; j < 8; j++)
            unpack2(acc2[ip][j], acc[2 * ip][j], acc[2 * ip + 1][j]);

    float xi[8], xj[8];
#pragma unroll
    for (int ii = 0; ii < 8; ii++) xi[ii] = g_xx[b * Nn + i0 + ty * 8 + ii];
#pragma unroll
    for (int jj = 0; jj < 8; jj++) xj[jj] = g_xx[b * Nn + j0 + tx * 8 + jj];

    float v[8][8];
#pragma unroll
    for (int ii = 0; ii < 8; ii++)
#pragma unroll
        for (int jj = 0; jj < 8; jj++)
            v[ii][jj] = 2.f * acc[ii][jj] - xi[ii] - xj[jj];

    // direct tile D[i][j]
#pragma unroll
    for (int ii = 0; ii < 8; ii++) {
        size_t base = ((size_t)b * Nn + i0 + ty * 8 + ii) * Nn + j0 + tx * 8;
        *(float4*)&g_D[base]     = make_float4(v[ii][0], v[ii][1], v[ii][2], v[ii][3]);
        *(float4*)&g_D[base + 4] = make_float4(v[ii][4], v[ii][5], v[ii][6], v[ii][7]);
    }
    // mirrored tile D[j][i] for off-diagonal block pairs
    if (bi != bj) {
#pragma unroll
        for (int jj = 0; jj < 8; jj++) {
            size_t base = ((size_t)b * Nn + j0 + tx * 8 + jj) * Nn + i0 + ty * 8;
            *(float4*)&g_D[base]     = make_float4(v[0][jj], v[1][jj], v[2][jj], v[3][jj]);
            *(float4*)&g_D[base + 4] = make_float4(v[4][jj], v[5][jj], v[6][jj], v[7][jj]);
        }
    }
}

// ---------------- 3. top-32 per row via 4-level radix select (set semantics) ----------------
__global__ void topk_kernel(int bpair) {
    int row = (bpair * 2 + blockIdx.y) * Nn + blockIdx.x;
    int t = threadIdx.x;                    // 256 threads
    int lane = t & 31, w = t >> 5;
    const float* Drow = g_D + (size_t)row * Nn;

    unsigned int u[8];
    {
        float4 f0 = *(const float4*)(Drow + 8 * t);
        float4 f1 = *(const float4*)(Drow + 8 * t + 4);
        float fv[8] = {f0.x, f0.y, f0.z, f0.w, f1.x, f1.y, f1.z, f1.w};
#pragma unroll
        for (int r = 0; r < 8; r++) {
            unsigned int bits = __float_as_uint(fv[r]);
            u[r] = (bits & 0x80000000u) ? ~bits : (bits | 0x80000000u);
        }
    }

    __shared__ unsigned int hist[256];
    __shared__ unsigned int warpsum[8];
    __shared__ unsigned int sb, sabove;
    __shared__ int tieList[2048];
    __shared__ int selCnt, tieCnt;

    unsigned int prefix = 0, pmask = 0;
    int need = KNB;

#pragma unroll
    for (int lvl = 0; lvl < 4; lvl++) {
        int shift = 24 - 8 * lvl;
        hist[t] = 0;
        __syncthreads();
#pragma unroll
        for (int r = 0; r < 8; r++)
            if ((u[r] & pmask) == prefix)
                atomicAdd(&hist[(u[r] >> shift) & 255u], 1u);
        __syncthreads();
        unsigned int hv = hist[t];
        unsigned int v = hv;
#pragma unroll
        for (int s = 1; s < 32; s <<= 1) {
            unsigned int o = __shfl_down_sync(0xffffffffu, v, s);
            if (lane + s < 32) v += o;
        }
        if (lane == 0) warpsum[w] = v;
        __syncthreads();
        unsigned int addw = 0;
        for (int j = w + 1; j < 8; j++) addw += warpsum[j];
        unsigned int hs_t = v + addw;
        unsigned int above = hs_t - hv;
        if (hs_t >= (unsigned int)need && above < (unsigned int)need) {
            sb = (unsigned int)t; sabove = above;
        }
        __syncthreads();
        prefix |= sb << shift;
        pmask  |= 0xFFu << shift;
        need   -= (int)sabove;
        __syncthreads();
    }

    unsigned int T = prefix;
    if (t == 0) { selCnt = 0; tieCnt = 0; }
    __syncthreads();
#pragma unroll
    for (int r = 0; r < 8; r++) {
        int gi = 8 * t + r;
        if (u[r] > T) {
            int pos = atomicAdd(&selCnt, 1);
            g_idx[row * KNB + pos] = gi;
        } else if (u[r] == T) {
            int pos = atomicAdd(&tieCnt, 1);
            tieList[pos] = gi;
        }
    }
    __syncthreads();
    if (t == 0) {
        int base = selCnt;
        for (int p2 = 0; p2 < need; p2++) {
            int best = 1 << 30, bj2 = -1;
            for (int j = 0; j < tieCnt; j++)
                if (tieList[j] < best) { best = tieList[j]; bj2 = j; }
            tieList[bj2] = 1 << 30;
            g_idx[row * KNB + base + p2] = best;
        }
    }
}

// ---------------- 4. projections, one matrix per blockIdx.z ----------------
__global__ void proj_kernel(const float* __restrict__ x,
                            const float* __restrict__ Wq,
                            const float* __restrict__ Wk,
                            const float* __restrict__ Wv) {
    int m = blockIdx.z;
    int b = blockIdx.y; int n0 = blockIdx.x * 64;
    const float* W = (m == 0) ? Wq : (m == 1) ? Wk : Wv;
    float* O       = (m == 0) ? g_Qt : (m == 1) ? g_Kt : g_Vt;
    __shared__ float Wt[64][68];       // [c][o]
    __shared__ float xs[64][68];       // [c][p]
    int t = threadIdx.x;
    const float* xb = x + (size_t)b * Cc * Nn;
    for (int idx = t; idx < 4096; idx += 256) {
        int c = idx >> 6, p = idx & 63;
        xs[c][p] = xb[c * Nn + n0 + p];
        int o = idx >> 6, c2 = idx & 63;
        Wt[c2][o] = W[idx];
    }
    __syncthreads();
    int tx = t & 15, ty = t >> 4;
    float acc[4][4] = {};
    for (int c = 0; c < 64; c++) {
        float4 wv4 = *(const float4*)&Wt[c][ty * 4];
        float4 xv4 = *(const float4*)&xs[c][tx * 4];
        float wr[4] = {wv4.x, wv4.y, wv4.z, wv4.w};
        float xr[4] = {xv4.x, xv4.y, xv4.z, xv4.w};
#pragma unroll
        for (int oi = 0; oi < 4; oi++)
#pragma unroll
            for (int pj = 0; pj < 4; pj++)
                acc[oi][pj] = fmaf(wr[oi], xr[pj], acc[oi][pj]);
    }
#pragma unroll
    for (int pj = 0; pj < 4; pj++) {
        int p = n0 + tx * 4 + pj;
        float4 val = make_float4(acc[0][pj], acc[1][pj], acc[2][pj], acc[3][pj]);
        *(float4*)&O[((size_t)(b * Nn + p)) * 64 + ty * 4] = val;
    }
}

// ---------------- 5. attention per point ----------------
__global__ void attn_kernel(const float* __restrict__ x) {
    int row = blockIdx.x;
    int b = row >> 11, n = row & (Nn - 1);
    int t = threadIdx.x;                       // 256 = 8 warps (1 head per warp)
    __shared__ float qv[64], kc[64], vc[64];
    __shared__ int   sid[32];
    if (t < 32)                sid[t]       = g_idx[row * KNB + t];
    else if (t >= 64  && t < 128) qv[t - 64]  = g_Qt[(size_t)row * 64 + (t - 64)];
    if (t >= 128 && t < 192) kc[t - 128] = g_Kt[(size_t)row * 64 + (t - 128)];
    else if (t >= 192)       vc[t - 192] = g_Vt[(size_t)row * 64 + (t - 192)];
    __syncthreads();

    int h = t >> 5, kk = t & 31;
    int nb = sid[kk];
    size_t nbbase = ((size_t)(b * Nn + nb)) * 64 + h * 8;
    const float* Kp = g_Kt + nbbase;
    float4 k0 = *(const float4*)(Kp);
    float4 k1 = *(const float4*)(Kp + 4);
    int h8 = h * 8;
    float e = 0.f;
    e = fmaf(qv[h8 + 0], k0.x - kc[h8 + 0], e);
    e = fmaf(qv[h8 + 1], k0.y - kc[h8 + 1], e);
    e = fmaf(qv[h8 + 2], k0.z - kc[h8 + 2], e);
    e = fmaf(qv[h8 + 3], k0.w - kc[h8 + 3], e);
    e = fmaf(qv[h8 + 4], k1.x - kc[h8 + 4], e);
    e = fmaf(qv[h8 + 5], k1.y - kc[h8 + 5], e);
    e = fmaf(qv[h8 + 6], k1.z - kc[h8 + 6], e);
    e = fmaf(qv[h8 + 7], k1.w - kc[h8 + 7], e);
    e *= 0.3535533905932738f;                 // 1/sqrt(8)

    float m = e;
#pragma unroll
    for (int s = 16; s; s >>= 1) m = fmaxf(m, __shfl_xor_sync(0xffffffffu, m, s));
    float ex = expf(e - m);
    float ssum = ex;
#pragma unroll
    for (int s = 16; s; s >>= 1) ssum += __shfl_xor_sync(0xffffffffu, ssum, s);
    float a = ex / ssum;

    const float* Vp = g_Vt + nbbase;
    float4 v0 = *(const float4*)(Vp);
    float4 v1 = *(const float4*)(Vp + 4);
    float vv[8] = {v0.x - vc[h8 + 0], v0.y - vc[h8 + 1], v0.z - vc[h8 + 2], v0.w - vc[h8 + 3],
                   v1.x - vc[h8 + 4], v1.y - vc[h8 + 5], v1.z - vc[h8 + 6], v1.w - vc[h8 + 7]};
#pragma unroll
    for (int d = 0; d < 8; d++) {
        float pd = a * vv[d];
#pragma unroll
        for (int s = 16; s; s >>= 1) pd += __shfl_xor_sync(0xffffffffu, pd, s);
        if (kk == d) {
            int c = h8 + d;
            size_t gi = (size_t)b * Cc * Nn + (size_t)c * Nn + n;
            g_y[gi] = x[gi] + pd;
        }
    }
}

// ---------------- 6/8. BN stats, two-stage ----------------
__global__ void statsA_kernel(int which) {
    const float* in = which ? g_y2 : g_y;
    int c = blockIdx.x, b = blockIdx.y, t = threadIdx.x;
    int lane = t & 31, w = t >> 5;
    const float* p = in + (size_t)b * Cc * Nn + (size_t)c * Nn;
    double s = 0.0, s2 = 0.0;
    for (int n = t; n < Nn; n += 256) { float v = p[n]; s += v; s2 += (double)v * v; }
#pragma unroll
    for (int o = 16; o; o >>= 1) {
        s  += __shfl_down_sync(0xffffffffu, s, o);
        s2 += __shfl_down_sync(0xffffffffu, s2, o);
    }
    __shared__ double ws[8], ws2[8];
    if (lane == 0) { ws[w] = s; ws2[w] = s2; }
    __syncthreads();
    if (t == 0) {
        double ts = 0.0, ts2 = 0.0;
        for (int j = 0; j < 8; j++) { ts += ws[j]; ts2 += ws2[j]; }
        g_ps[which][c][b] = ts;
        g_ps2[which][c][b] = ts2;
    }
}

__global__ void statsB_kernel(int which) {
    int c = blockIdx.x, t = threadIdx.x;       // 32 threads
    double s  = (t < Bb) ? g_ps[which][c][t]  : 0.0;
    double s2 = (t < Bb) ? g_ps2[which][c][t] : 0.0;
#pragma unroll
    for (int o = 4; o; o >>= 1) {
        s  += __shfl_down_sync(0xffffffffu, s, o);
        s2 += __shfl_down_sync(0xffffffffu, s2, o);
    }
    if (t == 0) {
        double m = s / (Bb * Nn);
        double var = s2 / (Bb * Nn) - m * m;
        float* mu = which ? g_mu2 : g_mu1;
        float* rs = which ? g_rs2 : g_rs1;
        mu[c] = (float)m;
        rs[c] = (float)(1.0 / sqrt(var + (double)EPSBN));
    }
}

// ---------------- 7. BN1 apply + FFN + residual ----------------
__global__ void ffn_kernel(const float* __restrict__ W1, const float* __restrict__ W2,
                           const float* __restrict__ g1, const float* __restrict__ b1) {
    int blk = blockIdx.x;
    int b = blk / (Nn / 16);
    int n0 = (blk % (Nn / 16)) * 16;
    __shared__ float Wbuf[128 * 64];
    __shared__ float x1s[64][17];
    __shared__ float hs[128][17];
    int t = threadIdx.x;

    for (int idx = t; idx < 64 * 16; idx += 256) {
        int c = idx >> 4, p = idx & 15;
        float v = g_y[(size_t)b * Cc * Nn + (size_t)c * Nn + n0 + p];
        x1s[c][p] = (v - g_mu1[c]) * g_rs1[c] * g1[c] + b1[c];
    }
    for (int idx = t; idx < 128 * 64; idx += 256) Wbuf[idx] = W1[idx];
    __syncthreads();

    int p = t & 15, obase = t >> 4;
    float hreg[8];
#pragma unroll
    for (int i = 0; i < 8; i++) {
        int o = obase + 16 * i;
        float s = 0.f;
#pragma unroll
        for (int c = 0; c < 64; c++) s = fmaf(Wbuf[o * 64 + c], x1s[c][p], s);
        hreg[i] = (s >= 0.f) ? s : NSLOPE * s;
    }
#pragma unroll
    for (int i = 0; i < 8; i++) hs[obase + 16 * i][p] = hreg[i];
    __syncthreads();
    for (int idx = t; idx < 64 * 128; idx += 256) Wbuf[idx] = W2[idx];
    __syncthreads();

#pragma unroll
    for (int i = 0; i < 4; i++) {
        int c = obase + 16 * i;
        float s = 0.f;
#pragma unroll
        for (int o = 0; o < 128; o++) s = fmaf(Wbuf[c * 128 + o], hs[o][p], s);
        g_y2[(size_t)b * Cc * Nn + (size_t)c * Nn + n0 + p] = x1s[c][p] + s;
    }
}

// ---------------- 9. final BN apply ----------------
__global__ void apply_kernel(const float* __restrict__ g2, const float* __restrict__ b2,
                             float* __restrict__ out) {
    int i = blockIdx.x * blockDim.x + threadIdx.x;
    if (i < Bb * Cc * Nn) {
        int c = (i / Nn) & (Cc - 1);
        out[i] = (g_y2[i] - g_mu2[c]) * g_rs2[c] * g2[c] + b2[c];
    }
}

// ---------------- launch ----------------
extern "C" void kernel_launch(void* const* d_in, const int* in_sizes, int n_in,
                              void* d_out, int out_size) {
    const float* x  = (const float*)d_in[0];
    const float* Wq = (const float*)d_in[1];
    const float* Wk = (const float*)d_in[2];
    const float* Wv = (const float*)d_in[3];
    const float* W1 = (const float*)d_in[4];
    const float* W2 = (const float*)d_in[5];
    const float* g1 = (const float*)d_in[6];
    const float* b1 = (const float*)d_in[7];
    const float* g2 = (const float*)d_in[8];
    const float* b2 = (const float*)d_in[9];
    float* out = (float*)d_out;

    xx_kernel<<<(Bb * Nn) / 256, 256>>>(x);
    proj_kernel<<<dim3(Nn / 64, Bb, 3), 256>>>(x, Wq, Wk, Wv);
    // interleave dist/topk at 2-batch granularity: each 32 MB D slice stays L2-resident
    for (int bp = 0; bp < Bb / 2; bp++) {
        dist_kernel<<<dim3(136, 2), 256>>>(x, bp);
        topk_kernel<<<dim3(Nn, 2), 256>>>(bp);
    }
    attn_kernel<<<Bb * Nn, 256>>>(x);
    statsA_kernel<<<dim3(Cc, Bb), 256>>>(0);
    statsB_kernel<<<Cc, 32>>>(0);
    ffn_kernel<<<Bb * Nn / 16, 256>>>(W1, W2, g1, b1);
    statsA_kernel<<<dim3(Cc, Bb), 256>>>(1);
    statsB_kernel<<<Cc, 32>>>(1);
    apply_kernel<<<(Bb * Cc * Nn + 255) / 256, 256>>>(g2, b2, out);
}

// round 10
// speedup vs baseline: 1.0876x; 1.0876x over previous
#include <cuda_runtime.h>
#include <math.h>

#define Bb   8
#define Cc   64
#define Nn   2048
#define KNB  32
#define NHEADS 8
#define EPSBN 1e-5f
#define NSLOPE 0.2f

// ---------------- scratch (device globals; no runtime allocation) ----------------
__device__ float g_xx[Bb * Nn];
__device__ float g_D[(size_t)Bb * Nn * Nn];             // 128 MB distance matrix
__device__ int   g_idx[Bb * Nn * KNB];
__device__ float g_Qt[(size_t)Bb * Nn * Cc];            // (B,N,64) point-major
__device__ float g_Kt[(size_t)Bb * Nn * Cc];
__device__ float g_Vt[(size_t)Bb * Nn * Cc];
__device__ float g_y [(size_t)Bb * Cc * Nn];
__device__ float g_y2[(size_t)Bb * Cc * Nn];
__device__ float g_mu1[Cc], g_rs1[Cc], g_mu2[Cc], g_rs2[Cc];
__device__ double g_ps [2][Cc][Bb];
__device__ double g_ps2[2][Cc][Bb];

// ---------------- packed f32x2 helpers (sm_103a FFMA2 path) ----------------
__device__ __forceinline__ unsigned long long pack2(float x, float y) {
    unsigned long long r;
    asm("mov.b64 %0, {%1, %2};" : "=l"(r) : "f"(x), "f"(y));
    return r;
}
__device__ __forceinline__ unsigned long long ffma2(unsigned long long a,
                                                    unsigned long long b,
                                                    unsigned long long c) {
    unsigned long long d;
    asm("fma.rn.f32x2 %0, %1, %2, %3;" : "=l"(d) : "l"(a), "l"(b), "l"(c));
    return d;
}
__device__ __forceinline__ void unpack2(unsigned long long v, float& lo, float& hi) {
    asm("mov.b64 {%0, %1}, %2;" : "=f"(lo), "=f"(hi) : "l"(v));
}

// ---------------- 1. squared norms ----------------
__global__ void xx_kernel(const float* __restrict__ x) {
    int i = blockIdx.x * blockDim.x + threadIdx.x;
    int b = i >> 11, n = i & (Nn - 1);
    const float* xp = x + (size_t)b * Cc * Nn + n;
    float s = 0.f;
#pragma unroll
    for (int c = 0; c < Cc; c++) { float v = xp[c * Nn]; s = fmaf(v, v, s); }
    g_xx[i] = s;
}

// ---------------- 2. neg squared distance matrix: symmetric upper-tri block pairs,
// packed f32x2 FMA inner loop ----------------
__global__ void __launch_bounds__(256, 2) dist_kernel(const float* __restrict__ x) {
    int b = blockIdx.z;
    // map blockIdx.x (0..135) -> (bi, bj) with bi <= bj over 16x16 tile grid
    int p = blockIdx.x, bi = 0;
    while (p >= 16 - bi) { p -= 16 - bi; bi++; }
    int bj = bi + p;
    int i0 = bi * 128, j0 = bj * 128;

    __shared__ float As[32][132];
    __shared__ float Bs[32][132];
    int t = threadIdx.x;
    int tx = t & 15, ty = t >> 4;                 // 16 x 16 threads, 8x8 tile each
    const float* xb = x + (size_t)b * Cc * Nn;

    unsigned long long acc2[4][8];                // acc pairs along ii
#pragma unroll
    for (int ip = 0; ip < 4; ip++)
#pragma unroll
        for (int j = 0; j < 8; j++) acc2[ip][j] = 0ull;

    for (int kc = 0; kc < Cc; kc += 32) {
        __syncthreads();
        for (int idx = t; idx < 32 * 128; idx += 256) {
            int c = idx >> 7, q = idx & 127;
            As[c][q] = xb[(kc + c) * Nn + i0 + q];
            Bs[c][q] = xb[(kc + c) * Nn + j0 + q];
        }
        __syncthreads();
#pragma unroll
        for (int c = 0; c < 32; c++) {
            ulonglong2 ap0 = *(const ulonglong2*)&As[c][ty * 8];       // (a0,a1),(a2,a3)
            ulonglong2 ap1 = *(const ulonglong2*)&As[c][ty * 8 + 4];   // (a4,a5),(a6,a7)
            unsigned long long ap[4] = {ap0.x, ap0.y, ap1.x, ap1.y};
            float4 b0 = *(const float4*)&Bs[c][tx * 8];
            float4 b1 = *(const float4*)&Bs[c][tx * 8 + 4];
            float bv[8] = {b0.x, b0.y, b0.z, b0.w, b1.x, b1.y, b1.z, b1.w};
            unsigned long long bc[8];
#pragma unroll
            for (int j = 0; j < 8; j++) bc[j] = pack2(bv[j], bv[j]);
#pragma unroll
            for (int ip = 0; ip < 4; ip++)
#pragma unroll
                for (int j = 0; j < 8; j++)
                    acc2[ip][j] = ffma2(ap[ip], bc[j], acc2[ip][j]);
        }
    }

    float acc[8][8];
#pragma unroll
    for (int ip = 0; ip < 4; ip++)
#pragma unroll
        for (int j = 0; j < 8; j++)
            unpack2(acc2[ip][j], acc[2 * ip][j], acc[2 * ip + 1][j]);

    float xi[8], xj[8];
#pragma unroll
    for (int ii = 0; ii < 8; ii++) xi[ii] = g_xx[b * Nn + i0 + ty * 8 + ii];
#pragma unroll
    for (int jj = 0; jj < 8; jj++) xj[jj] = g_xx[b * Nn + j0 + tx * 8 + jj];

    float v[8][8];
#pragma unroll
    for (int ii = 0; ii < 8; ii++)
#pragma unroll
        for (int jj = 0; jj < 8; jj++)
            v[ii][jj] = 2.f * acc[ii][jj] - xi[ii] - xj[jj];

    // direct tile D[i][j]
#pragma unroll
    for (int ii = 0; ii < 8; ii++) {
        size_t base = ((size_t)b * Nn + i0 + ty * 8 + ii) * Nn + j0 + tx * 8;
        *(float4*)&g_D[base]     = make_float4(v[ii][0], v[ii][1], v[ii][2], v[ii][3]);
        *(float4*)&g_D[base + 4] = make_float4(v[ii][4], v[ii][5], v[ii][6], v[ii][7]);
    }
    // mirrored tile D[j][i] for off-diagonal block pairs
    if (bi != bj) {
#pragma unroll
        for (int jj = 0; jj < 8; jj++) {
            size_t base = ((size_t)b * Nn + j0 + tx * 8 + jj) * Nn + i0 + ty * 8;
            *(float4*)&g_D[base]     = make_float4(v[0][jj], v[1][jj], v[2][jj], v[3][jj]);
            *(float4*)&g_D[base + 4] = make_float4(v[4][jj], v[5][jj], v[6][jj], v[7][jj]);
        }
    }
}

// ---------------- 3. top-32 per row: 2-level radix (16-bit prefix) + warp micro-select
// over the candidate bin. Set semantics; min-index tiebreak via composite key. ----------------
__global__ void topk_kernel() {
    int row = blockIdx.x;
    int t = threadIdx.x;                    // 256 threads
    int lane = t & 31, w = t >> 5;
    const float* Drow = g_D + (size_t)row * Nn;

    unsigned int u[8];
    {
        float4 f0 = *(const float4*)(Drow + 8 * t);
        float4 f1 = *(const float4*)(Drow + 8 * t + 4);
        float fv[8] = {f0.x, f0.y, f0.z, f0.w, f1.x, f1.y, f1.z, f1.w};
#pragma unroll
        for (int r = 0; r < 8; r++) {
            unsigned int bits = __float_as_uint(fv[r]);
            u[r] = (bits & 0x80000000u) ? ~bits : (bits | 0x80000000u);
        }
    }

    __shared__ unsigned int hist[256];
    __shared__ unsigned int warpsum[8];
    __shared__ unsigned int sb, sabove;
    __shared__ unsigned long long cand[2048];
    __shared__ int selCnt, candCnt, needSh;

    unsigned int prefix = 0, pmask = 0;
    int need = KNB;

#pragma unroll
    for (int lvl = 0; lvl < 2; lvl++) {
        int shift = 24 - 8 * lvl;
        hist[t] = 0;
        __syncthreads();
#pragma unroll
        for (int r = 0; r < 8; r++)
            if ((u[r] & pmask) == prefix)
                atomicAdd(&hist[(u[r] >> shift) & 255u], 1u);
        __syncthreads();
        unsigned int hv = hist[t];
        unsigned int v = hv;
#pragma unroll
        for (int s = 1; s < 32; s <<= 1) {
            unsigned int o = __shfl_down_sync(0xffffffffu, v, s);
            if (lane + s < 32) v += o;
        }
        if (lane == 0) warpsum[w] = v;
        __syncthreads();
        unsigned int addw = 0;
        for (int j = w + 1; j < 8; j++) addw += warpsum[j];
        unsigned int hs_t = v + addw;          // elems in bins >= t (within prefix class)
        unsigned int above = hs_t - hv;        // elems in bins > t
        if (hs_t >= (unsigned int)need && above < (unsigned int)need) {
            sb = (unsigned int)t; sabove = above;
        }
        __syncthreads();
        prefix |= sb << shift;
        pmask  |= 0xFFu << shift;
        need   -= (int)sabove;
        __syncthreads();
    }

    // prefix/pmask now cover the top 16 bits. Emit strict-above directly; compact the
    // candidate bin (same 16-bit prefix) as composite (key<<32 | 2047-idx).
    if (t == 0) { selCnt = 0; candCnt = 0; needSh = need; }
    __syncthreads();
#pragma unroll
    for (int r = 0; r < 8; r++) {
        int gi = 8 * t + r;
        unsigned int masked = u[r] & pmask;
        if (masked > prefix) {
            int pos = atomicAdd(&selCnt, 1);
            g_idx[row * KNB + pos] = gi;
        } else if (masked == prefix) {
            int pos = atomicAdd(&candCnt, 1);
            cand[pos] = ((unsigned long long)u[r] << 32) | (unsigned int)(2047 - gi);
        }
    }
    __syncthreads();

    // one warp peels the remaining `need` maxima from the candidate list (exact)
    if (w == 0) {
        int m = candCnt;
        int base = selCnt;                     // == KNB - need
        int nd = needSh;
        for (int p2 = 0; p2 < nd; p2++) {
            unsigned long long best = 0ull;
            for (int j = lane; j < m; j += 32)
                best = (cand[j] > best) ? cand[j] : best;
#pragma unroll
            for (int s = 16; s; s >>= 1) {
                unsigned long long o = __shfl_xor_sync(0xffffffffu, best, s);
                best = (o > best) ? o : best;
            }
            if (lane == 0)
                g_idx[row * KNB + base + p2] = 2047 - (int)(best & 0xFFFFFFFFull);
            for (int j = lane; j < m; j += 32)
                if (cand[j] == best) cand[j] = 0ull;
        }
    }
}

// ---------------- 4. projections, one matrix per blockIdx.z ----------------
__global__ void proj_kernel(const float* __restrict__ x,
                            const float* __restrict__ Wq,
                            const float* __restrict__ Wk,
                            const float* __restrict__ Wv) {
    int m = blockIdx.z;
    int b = blockIdx.y; int n0 = blockIdx.x * 64;
    const float* W = (m == 0) ? Wq : (m == 1) ? Wk : Wv;
    float* O       = (m == 0) ? g_Qt : (m == 1) ? g_Kt : g_Vt;
    __shared__ float Wt[64][68];       // [c][o]
    __shared__ float xs[64][68];       // [c][p]
    int t = threadIdx.x;
    const float* xb = x + (size_t)b * Cc * Nn;
    for (int idx = t; idx < 4096; idx += 256) {
        int c = idx >> 6, p = idx & 63;
        xs[c][p] = xb[c * Nn + n0 + p];
        int o = idx >> 6, c2 = idx & 63;
        Wt[c2][o] = W[idx];
    }
    __syncthreads();
    int tx = t & 15, ty = t >> 4;
    float acc[4][4] = {};
    for (int c = 0; c < 64; c++) {
        float4 wv4 = *(const float4*)&Wt[c][ty * 4];
        float4 xv4 = *(const float4*)&xs[c][tx * 4];
        float wr[4] = {wv4.x, wv4.y, wv4.z, wv4.w};
        float xr[4] = {xv4.x, xv4.y, xv4.z, xv4.w};
#pragma unroll
        for (int oi = 0; oi < 4; oi++)
#pragma unroll
            for (int pj = 0; pj < 4; pj++)
                acc[oi][pj] = fmaf(wr[oi], xr[pj], acc[oi][pj]);
    }
#pragma unroll
    for (int pj = 0; pj < 4; pj++) {
        int p = n0 + tx * 4 + pj;
        float4 val = make_float4(acc[0][pj], acc[1][pj], acc[2][pj], acc[3][pj]);
        *(float4*)&O[((size_t)(b * Nn + p)) * 64 + ty * 4] = val;
    }
}

// ---------------- 5. attention per point ----------------
__global__ void attn_kernel(const float* __restrict__ x) {
    int row = blockIdx.x;
    int b = row >> 11, n = row & (Nn - 1);
    int t = threadIdx.x;                       // 256 = 8 warps (1 head per warp)
    __shared__ float qv[64], kc[64], vc[64];
    __shared__ int   sid[32];
    if (t < 32)                sid[t]       = g_idx[row * KNB + t];
    else if (t >= 64  && t < 128) qv[t - 64]  = g_Qt[(size_t)row * 64 + (t - 64)];
    if (t >= 128 && t < 192) kc[t - 128] = g_Kt[(size_t)row * 64 + (t - 128)];
    else if (t >= 192)       vc[t - 192] = g_Vt[(size_t)row * 64 + (t - 192)];
    __syncthreads();

    int h = t >> 5, kk = t & 31;
    int nb = sid[kk];
    size_t nbbase = ((size_t)(b * Nn + nb)) * 64 + h * 8;
    const float* Kp = g_Kt + nbbase;
    float4 k0 = *(const float4*)(Kp);
    float4 k1 = *(const float4*)(Kp + 4);
    int h8 = h * 8;
    float e = 0.f;
    e = fmaf(qv[h8 + 0], k0.x - kc[h8 + 0], e);
    e = fmaf(qv[h8 + 1], k0.y - kc[h8 + 1], e);
    e = fmaf(qv[h8 + 2], k0.z - kc[h8 + 2], e);
    e = fmaf(qv[h8 + 3], k0.w - kc[h8 + 3], e);
    e = fmaf(qv[h8 + 4], k1.x - kc[h8 + 4], e);
    e = fmaf(qv[h8 + 5], k1.y - kc[h8 + 5], e);
    e = fmaf(qv[h8 + 6], k1.z - kc[h8 + 6], e);
    e = fmaf(qv[h8 + 7], k1.w - kc[h8 + 7], e);
    e *= 0.3535533905932738f;                 // 1/sqrt(8)

    float m = e;
#pragma unroll
    for (int s = 16; s; s >>= 1) m = fmaxf(m, __shfl_xor_sync(0xffffffffu, m, s));
    float ex = expf(e - m);
    float ssum = ex;
#pragma unroll
    for (int s = 16; s; s >>= 1) ssum += __shfl_xor_sync(0xffffffffu, ssum, s);
    float a = ex / ssum;

    const float* Vp = g_Vt + nbbase;
    float4 v0 = *(const float4*)(Vp);
    float4 v1 = *(const float4*)(Vp + 4);
    float vv[8] = {v0.x - vc[h8 + 0], v0.y - vc[h8 + 1], v0.z - vc[h8 + 2], v0.w - vc[h8 + 3],
                   v1.x - vc[h8 + 4], v1.y - vc[h8 + 5], v1.z - vc[h8 + 6], v1.w - vc[h8 + 7]};
#pragma unroll
    for (int d = 0; d < 8; d++) {
        float pd = a * vv[d];
#pragma unroll
        for (int s = 16; s; s >>= 1) pd += __shfl_xor_sync(0xffffffffu, pd, s);
        if (kk == d) {
            int c = h8 + d;
            size_t gi = (size_t)b * Cc * Nn + (size_t)c * Nn + n;
            g_y[gi] = x[gi] + pd;
        }
    }
}

// ---------------- 6/8. BN stats, two-stage ----------------
__global__ void statsA_kernel(int which) {
    const float* in = which ? g_y2 : g_y;
    int c = blockIdx.x, b = blockIdx.y, t = threadIdx.x;
    int lane = t & 31, w = t >> 5;
    const float* p = in + (size_t)b * Cc * Nn + (size_t)c * Nn;
    double s = 0.0, s2 = 0.0;
    for (int n = t; n < Nn; n += 256) { float v = p[n]; s += v; s2 += (double)v * v; }
#pragma unroll
    for (int o = 16; o; o >>= 1) {
        s  += __shfl_down_sync(0xffffffffu, s, o);
        s2 += __shfl_down_sync(0xffffffffu, s2, o);
    }
    __shared__ double ws[8], ws2[8];
    if (lane == 0) { ws[w] = s; ws2[w] = s2; }
    __syncthreads();
    if (t == 0) {
        double ts = 0.0, ts2 = 0.0;
        for (int j = 0; j < 8; j++) { ts += ws[j]; ts2 += ws2[j]; }
        g_ps[which][c][b] = ts;
        g_ps2[which][c][b] = ts2;
    }
}

__global__ void statsB_kernel(int which) {
    int c = blockIdx.x, t = threadIdx.x;       // 32 threads
    double s  = (t < Bb) ? g_ps[which][c][t]  : 0.0;
    double s2 = (t < Bb) ? g_ps2[which][c][t] : 0.0;
#pragma unroll
    for (int o = 4; o; o >>= 1) {
        s  += __shfl_down_sync(0xffffffffu, s, o);
        s2 += __shfl_down_sync(0xffffffffu, s2, o);
    }
    if (t == 0) {
        double m = s / (Bb * Nn);
        double var = s2 / (Bb * Nn) - m * m;
        float* mu = which ? g_mu2 : g_mu1;
        float* rs = which ? g_rs2 : g_rs1;
        mu[c] = (float)m;
        rs[c] = (float)(1.0 / sqrt(var + (double)EPSBN));
    }
}

// ---------------- 7. BN1 apply + FFN + residual ----------------
__global__ void ffn_kernel(const float* __restrict__ W1, const float* __restrict__ W2,
                           const float* __restrict__ g1, const float* __restrict__ b1) {
    int blk = blockIdx.x;
    int b = blk / (Nn / 16);
    int n0 = (blk % (Nn / 16)) * 16;
    __shared__ float Wbuf[128 * 64];
    __shared__ float x1s[64][17];
    __shared__ float hs[128][17];
    int t = threadIdx.x;

    for (int idx = t; idx < 64 * 16; idx += 256) {
        int c = idx >> 4, p = idx & 15;
        float v = g_y[(size_t)b * Cc * Nn + (size_t)c * Nn + n0 + p];
        x1s[c][p] = (v - g_mu1[c]) * g_rs1[c] * g1[c] + b1[c];
    }
    for (int idx = t; idx < 128 * 64; idx += 256) Wbuf[idx] = W1[idx];
    __syncthreads();

    int p = t & 15, obase = t >> 4;
    float hreg[8];
#pragma unroll
    for (int i = 0; i < 8; i++) {
        int o = obase + 16 * i;
        float s = 0.f;
#pragma unroll
        for (int c = 0; c < 64; c++) s = fmaf(Wbuf[o * 64 + c], x1s[c][p], s);
        hreg[i] = (s >= 0.f) ? s : NSLOPE * s;
    }
#pragma unroll
    for (int i = 0; i < 8; i++) hs[obase + 16 * i][p] = hreg[i];
    __syncthreads();
    for (int idx = t; idx < 64 * 128; idx += 256) Wbuf[idx] = W2[idx];
    __syncthreads();

#pragma unroll
    for (int i = 0; i < 4; i++) {
        int c = obase + 16 * i;
        float s = 0.f;
#pragma unroll
        for (int o = 0; o < 128; o++) s = fmaf(Wbuf[c * 128 + o], hs[o][p], s);
        g_y2[(size_t)b * Cc * Nn + (size_t)c * Nn + n0 + p] = x1s[c][p] + s;
    }
}

// ---------------- 9. final BN apply ----------------
__global__ void apply_kernel(const float* __restrict__ g2, const float* __restrict__ b2,
                             float* __restrict__ out) {
    int i = blockIdx.x * blockDim.x + threadIdx.x;
    if (i < Bb * Cc * Nn) {
        int c = (i / Nn) & (Cc - 1);
        out[i] = (g_y2[i] - g_mu2[c]) * g_rs2[c] * g2[c] + b2[c];
    }
}

// ---------------- launch ----------------
extern "C" void kernel_launch(void* const* d_in, const int* in_sizes, int n_in,
                              void* d_out, int out_size) {
    const float* x  = (const float*)d_in[0];
    const float* Wq = (const float*)d_in[1];
    const float* Wk = (const float*)d_in[2];
    const float* Wv = (const float*)d_in[3];
    const float* W1 = (const float*)d_in[4];
    const float* W2 = (const float*)d_in[5];
    const float* g1 = (const float*)d_in[6];
    const float* b1 = (const float*)d_in[7];
    const float* g2 = (const float*)d_in[8];
    const float* b2 = (const float*)d_in[9];
    float* out = (float*)d_out;

    xx_kernel<<<(Bb * Nn) / 256, 256>>>(x);
    dist_kernel<<<dim3(136, 1, Bb), 256>>>(x);
    topk_kernel<<<Bb * Nn, 256>>>();
    proj_kernel<<<dim3(Nn / 64, Bb, 3), 256>>>(x, Wq, Wk, Wv);
    attn_kernel<<<Bb * Nn, 256>>>(x);
    statsA_kernel<<<dim3(Cc, Bb), 256>>>(0);
    statsB_kernel<<<Cc, 32>>>(0);
    ffn_kernel<<<Bb * Nn / 16, 256>>>(W1, W2, g1, b1);
    statsA_kernel<<<dim3(Cc, Bb), 256>>>(1);
    statsB_kernel<<<Cc, 32>>>(1);
    apply_kernel<<<(Bb * Cc * Nn + 255) / 256, 256>>>(g2, b2, out);
}

// round 11
// speedup vs baseline: 1.1262x; 1.0355x over previous
#include <cuda_runtime.h>
#include <math.h>

#define Bb   8
#define Cc   64
#define Nn   2048
#define KNB  32
#define NHEADS 8
#define EPSBN 1e-5f
#define NSLOPE 0.2f

// ---------------- scratch (device globals; no runtime allocation) ----------------
__device__ float g_xx[Bb * Nn];
__device__ float g_D[(size_t)Bb * Nn * Nn];             // 128 MB distance matrix
__device__ int   g_idx[Bb * Nn * KNB];
__device__ float g_Qt[(size_t)Bb * Nn * Cc];            // (B,N,64) point-major
__device__ float g_Kt[(size_t)Bb * Nn * Cc];
__device__ float g_Vt[(size_t)Bb * Nn * Cc];
__device__ float g_y [(size_t)Bb * Cc * Nn];
__device__ float g_y2[(size_t)Bb * Cc * Nn];
__device__ float g_mu1[Cc], g_rs1[Cc], g_mu2[Cc], g_rs2[Cc];
__device__ double g_ps [2][Cc][Bb];
__device__ double g_ps2[2][Cc][Bb];
__device__ int    g_cnt[2];                              // zero-init; self-resetting

// ---------------- packed f32x2 helpers (sm_103a FFMA2 path) ----------------
__device__ __forceinline__ unsigned long long pack2(float x, float y) {
    unsigned long long r;
    asm("mov.b64 %0, {%1, %2};" : "=l"(r) : "f"(x), "f"(y));
    return r;
}
__device__ __forceinline__ unsigned long long ffma2(unsigned long long a,
                                                    unsigned long long b,
                                                    unsigned long long c) {
    unsigned long long d;
    asm("fma.rn.f32x2 %0, %1, %2, %3;" : "=l"(d) : "l"(a), "l"(b), "l"(c));
    return d;
}
__device__ __forceinline__ void unpack2(unsigned long long v, float& lo, float& hi) {
    asm("mov.b64 {%0, %1}, %2;" : "=f"(lo), "=f"(hi) : "l"(v));
}

// ---------------- 1. fused squared norms + Q/K/V projections ----------------
// dynamic smem: xs[64][68] then Wt[3*64][68]
extern __shared__ float dynsmem[];
__global__ void qkv_kernel(const float* __restrict__ x,
                           const float* __restrict__ Wq,
                           const float* __restrict__ Wk,
                           const float* __restrict__ Wv) {
    float (*xs)[68] = (float(*)[68])dynsmem;
    float (*Wt)[68] = (float(*)[68])(dynsmem + 64 * 68);
    int b = blockIdx.y, n0 = blockIdx.x * 64;
    int t = threadIdx.x;
    const float* xb = x + (size_t)b * Cc * Nn;
    for (int idx = t; idx < 4096; idx += 256) {
        int c = idx >> 6, p = idx & 63;
        xs[c][p] = xb[c * Nn + n0 + p];
    }
    const float* Ws[3] = {Wq, Wk, Wv};
#pragma unroll
    for (int m = 0; m < 3; m++)
        for (int idx = t; idx < 4096; idx += 256) {
            int o = idx >> 6, c = idx & 63;
            Wt[m * 64 + c][o] = Ws[m][idx];
        }
    __syncthreads();

    if (t < 64) {                                  // squared norms for these 64 points
        float s = 0.f;
#pragma unroll
        for (int c = 0; c < 64; c++) s = fmaf(xs[c][t], xs[c][t], s);
        g_xx[b * Nn + n0 + t] = s;
    }

    int tx = t & 15, ty = t >> 4;
    float acc[3][4][4] = {};
    for (int c = 0; c < 64; c++) {
        float4 xv4 = *(const float4*)&xs[c][tx * 4];
        float xr[4] = {xv4.x, xv4.y, xv4.z, xv4.w};
#pragma unroll
        for (int m = 0; m < 3; m++) {
            float4 wv4 = *(const float4*)&Wt[m * 64 + c][ty * 4];
            float wr[4] = {wv4.x, wv4.y, wv4.z, wv4.w};
#pragma unroll
            for (int oi = 0; oi < 4; oi++)
#pragma unroll
                for (int pj = 0; pj < 4; pj++)
                    acc[m][oi][pj] = fmaf(wr[oi], xr[pj], acc[m][oi][pj]);
        }
    }
    float* Olist[3] = {g_Qt, g_Kt, g_Vt};
#pragma unroll
    for (int m = 0; m < 3; m++)
#pragma unroll
        for (int pj = 0; pj < 4; pj++) {
            int p = n0 + tx * 4 + pj;
            float4 val = make_float4(acc[m][0][pj], acc[m][1][pj], acc[m][2][pj], acc[m][3][pj]);
            *(float4*)&Olist[m][((size_t)(b * Nn + p)) * 64 + ty * 4] = val;
        }
}

// ---------------- 2. neg squared distance matrix: symmetric upper-tri block pairs,
// packed f32x2 FMA inner loop ----------------
__global__ void __launch_bounds__(256, 2) dist_kernel(const float* __restrict__ x) {
    int b = blockIdx.z;
    int p = blockIdx.x, bi = 0;
    while (p >= 16 - bi) { p -= 16 - bi; bi++; }
    int bj = bi + p;
    int i0 = bi * 128, j0 = bj * 128;

    __shared__ float As[32][132];
    __shared__ float Bs[32][132];
    int t = threadIdx.x;
    int tx = t & 15, ty = t >> 4;
    const float* xb = x + (size_t)b * Cc * Nn;

    unsigned long long acc2[4][8];
#pragma unroll
    for (int ip = 0; ip < 4; ip++)
#pragma unroll
        for (int j = 0; j < 8; j++) acc2[ip][j] = 0ull;

    for (int kc = 0; kc < Cc; kc += 32) {
        __syncthreads();
        for (int idx = t; idx < 32 * 128; idx += 256) {
            int c = idx >> 7, q = idx & 127;
            As[c][q] = xb[(kc + c) * Nn + i0 + q];
            Bs[c][q] = xb[(kc + c) * Nn + j0 + q];
        }
        __syncthreads();
#pragma unroll
        for (int c = 0; c < 32; c++) {
            ulonglong2 ap0 = *(const ulonglong2*)&As[c][ty * 8];
            ulonglong2 ap1 = *(const ulonglong2*)&As[c][ty * 8 + 4];
            unsigned long long ap[4] = {ap0.x, ap0.y, ap1.x, ap1.y};
            float4 b0 = *(const float4*)&Bs[c][tx * 8];
            float4 b1 = *(const float4*)&Bs[c][tx * 8 + 4];
            float bv[8] = {b0.x, b0.y, b0.z, b0.w, b1.x, b1.y, b1.z, b1.w};
            unsigned long long bc[8];
#pragma unroll
            for (int j = 0; j < 8; j++) bc[j] = pack2(bv[j], bv[j]);
#pragma unroll
            for (int ip = 0; ip < 4; ip++)
#pragma unroll
                for (int j = 0; j < 8; j++)
                    acc2[ip][j] = ffma2(ap[ip], bc[j], acc2[ip][j]);
        }
    }

    float acc[8][8];
#pragma unroll
    for (int ip = 0; ip < 4; ip++)
#pragma unroll
        for (int j = 0; j < 8; j++)
            unpack2(acc2[ip][j], acc[2 * ip][j], acc[2 * ip + 1][j]);

    float xi[8], xj[8];
#pragma unroll
    for (int ii = 0; ii < 8; ii++) xi[ii] = g_xx[b * Nn + i0 + ty * 8 + ii];
#pragma unroll
    for (int jj = 0; jj < 8; jj++) xj[jj] = g_xx[b * Nn + j0 + tx * 8 + jj];

    float v[8][8];
#pragma unroll
    for (int ii = 0; ii < 8; ii++)
#pragma unroll
        for (int jj = 0; jj < 8; jj++)
            v[ii][jj] = 2.f * acc[ii][jj] - xi[ii] - xj[jj];

#pragma unroll
    for (int ii = 0; ii < 8; ii++) {
        size_t base = ((size_t)b * Nn + i0 + ty * 8 + ii) * Nn + j0 + tx * 8;
        *(float4*)&g_D[base]     = make_float4(v[ii][0], v[ii][1], v[ii][2], v[ii][3]);
        *(float4*)&g_D[base + 4] = make_float4(v[ii][4], v[ii][5], v[ii][6], v[ii][7]);
    }
    if (bi != bj) {
#pragma unroll
        for (int jj = 0; jj < 8; jj++) {
            size_t base = ((size_t)b * Nn + j0 + tx * 8 + jj) * Nn + i0 + ty * 8;
            *(float4*)&g_D[base]     = make_float4(v[0][jj], v[1][jj], v[2][jj], v[3][jj]);
            *(float4*)&g_D[base + 4] = make_float4(v[4][jj], v[5][jj], v[6][jj], v[7][jj]);
        }
    }
}

// ---------------- 3. top-32 per row: 2-level radix (16-bit prefix) + warp micro-select ----------------
__global__ void topk_kernel() {
    int row = blockIdx.x;
    int t = threadIdx.x;                    // 256 threads
    int lane = t & 31, w = t >> 5;
    const float* Drow = g_D + (size_t)row * Nn;

    unsigned int u[8];
    {
        float4 f0 = *(const float4*)(Drow + 8 * t);
        float4 f1 = *(const float4*)(Drow + 8 * t + 4);
        float fv[8] = {f0.x, f0.y, f0.z, f0.w, f1.x, f1.y, f1.z, f1.w};
#pragma unroll
        for (int r = 0; r < 8; r++) {
            unsigned int bits = __float_as_uint(fv[r]);
            u[r] = (bits & 0x80000000u) ? ~bits : (bits | 0x80000000u);
        }
    }

    __shared__ unsigned int hist[256];
    __shared__ unsigned int warpsum[8];
    __shared__ unsigned int sb, sabove;
    __shared__ unsigned long long cand[2048];
    __shared__ int selCnt, candCnt, needSh;

    unsigned int prefix = 0, pmask = 0;
    int need = KNB;

#pragma unroll
    for (int lvl = 0; lvl < 2; lvl++) {
        int shift = 24 - 8 * lvl;
        hist[t] = 0;
        __syncthreads();
#pragma unroll
        for (int r = 0; r < 8; r++)
            if ((u[r] & pmask) == prefix)
                atomicAdd(&hist[(u[r] >> shift) & 255u], 1u);
        __syncthreads();
        unsigned int hv = hist[t];
        unsigned int v = hv;
#pragma unroll
        for (int s = 1; s < 32; s <<= 1) {
            unsigned int o = __shfl_down_sync(0xffffffffu, v, s);
            if (lane + s < 32) v += o;
        }
        if (lane == 0) warpsum[w] = v;
        __syncthreads();
        unsigned int addw = 0;
        for (int j = w + 1; j < 8; j++) addw += warpsum[j];
        unsigned int hs_t = v + addw;
        unsigned int above = hs_t - hv;
        if (hs_t >= (unsigned int)need && above < (unsigned int)need) {
            sb = (unsigned int)t; sabove = above;
        }
        __syncthreads();
        prefix |= sb << shift;
        pmask  |= 0xFFu << shift;
        need   -= (int)sabove;
        __syncthreads();
    }

    if (t == 0) { selCnt = 0; candCnt = 0; needSh = need; }
    __syncthreads();
#pragma unroll
    for (int r = 0; r < 8; r++) {
        int gi = 8 * t + r;
        unsigned int masked = u[r] & pmask;
        if (masked > prefix) {
            int pos = atomicAdd(&selCnt, 1);
            g_idx[row * KNB + pos] = gi;
        } else if (masked == prefix) {
            int pos = atomicAdd(&candCnt, 1);
            cand[pos] = ((unsigned long long)u[r] << 32) | (unsigned int)(2047 - gi);
        }
    }
    __syncthreads();

    if (w == 0) {
        int m = candCnt;
        int base = selCnt;
        int nd = needSh;
        for (int p2 = 0; p2 < nd; p2++) {
            unsigned long long best = 0ull;
            for (int j = lane; j < m; j += 32)
                best = (cand[j] > best) ? cand[j] : best;
#pragma unroll
            for (int s = 16; s; s >>= 1) {
                unsigned long long o = __shfl_xor_sync(0xffffffffu, best, s);
                best = (o > best) ? o : best;
            }
            if (lane == 0)
                g_idx[row * KNB + base + p2] = 2047 - (int)(best & 0xFFFFFFFFull);
            for (int j = lane; j < m; j += 32)
                if (cand[j] == best) cand[j] = 0ull;
        }
    }
}

// ---------------- 5. attention per point ----------------
__global__ void attn_kernel(const float* __restrict__ x) {
    int row = blockIdx.x;
    int b = row >> 11, n = row & (Nn - 1);
    int t = threadIdx.x;                       // 256 = 8 warps (1 head per warp)
    __shared__ float qv[64], kc[64], vc[64];
    __shared__ int   sid[32];
    if (t < 32)                sid[t]       = g_idx[row * KNB + t];
    else if (t >= 64  && t < 128) qv[t - 64]  = g_Qt[(size_t)row * 64 + (t - 64)];
    if (t >= 128 && t < 192) kc[t - 128] = g_Kt[(size_t)row * 64 + (t - 128)];
    else if (t >= 192)       vc[t - 192] = g_Vt[(size_t)row * 64 + (t - 192)];
    __syncthreads();

    int h = t >> 5, kk = t & 31;
    int nb = sid[kk];
    size_t nbbase = ((size_t)(b * Nn + nb)) * 64 + h * 8;
    const float* Kp = g_Kt + nbbase;
    float4 k0 = *(const float4*)(Kp);
    float4 k1 = *(const float4*)(Kp + 4);
    int h8 = h * 8;
    float e = 0.f;
    e = fmaf(qv[h8 + 0], k0.x - kc[h8 + 0], e);
    e = fmaf(qv[h8 + 1], k0.y - kc[h8 + 1], e);
    e = fmaf(qv[h8 + 2], k0.z - kc[h8 + 2], e);
    e = fmaf(qv[h8 + 3], k0.w - kc[h8 + 3], e);
    e = fmaf(qv[h8 + 4], k1.x - kc[h8 + 4], e);
    e = fmaf(qv[h8 + 5], k1.y - kc[h8 + 5], e);
    e = fmaf(qv[h8 + 6], k1.z - kc[h8 + 6], e);
    e = fmaf(qv[h8 + 7], k1.w - kc[h8 + 7], e);
    e *= 0.3535533905932738f;                 // 1/sqrt(8)

    float m = e;
#pragma unroll
    for (int s = 16; s; s >>= 1) m = fmaxf(m, __shfl_xor_sync(0xffffffffu, m, s));
    float ex = expf(e - m);
    float ssum = ex;
#pragma unroll
    for (int s = 16; s; s >>= 1) ssum += __shfl_xor_sync(0xffffffffu, ssum, s);
    float a = ex / ssum;

    const float* Vp = g_Vt + nbbase;
    float4 v0 = *(const float4*)(Vp);
    float4 v1 = *(const float4*)(Vp + 4);
    float vv[8] = {v0.x - vc[h8 + 0], v0.y - vc[h8 + 1], v0.z - vc[h8 + 2], v0.w - vc[h8 + 3],
                   v1.x - vc[h8 + 4], v1.y - vc[h8 + 5], v1.z - vc[h8 + 6], v1.w - vc[h8 + 7]};
#pragma unroll
    for (int d = 0; d < 8; d++) {
        float pd = a * vv[d];
#pragma unroll
        for (int s = 16; s; s >>= 1) pd += __shfl_xor_sync(0xffffffffu, pd, s);
        if (kk == d) {
            int c = h8 + d;
            size_t gi = (size_t)b * Cc * Nn + (size_t)c * Nn + n;
            g_y[gi] = x[gi] + pd;
        }
    }
}

// ---------------- 6/8. BN stats, single kernel with last-block finalize ----------------
__global__ void statsA_kernel(int which) {
    const float* in = which ? g_y2 : g_y;
    int c = blockIdx.x, b = blockIdx.y, t = threadIdx.x;
    int lane = t & 31, w = t >> 5;
    const float* p = in + (size_t)b * Cc * Nn + (size_t)c * Nn;
    double s = 0.0, s2 = 0.0;
    for (int n = t; n < Nn; n += 256) { float v = p[n]; s += v; s2 += (double)v * v; }
#pragma unroll
    for (int o = 16; o; o >>= 1) {
        s  += __shfl_down_sync(0xffffffffu, s, o);
        s2 += __shfl_down_sync(0xffffffffu, s2, o);
    }
    __shared__ double ws[8], ws2[8];
    __shared__ int isLast;
    if (lane == 0) { ws[w] = s; ws2[w] = s2; }
    __syncthreads();
    if (t == 0) {
        double ts = 0.0, ts2 = 0.0;
        for (int j = 0; j < 8; j++) { ts += ws[j]; ts2 += ws2[j]; }
        g_ps[which][c][b] = ts;
        g_ps2[which][c][b] = ts2;
        __threadfence();
        int v = atomicAdd(&g_cnt[which], 1);
        isLast = (v == Cc * Bb - 1);
    }
    __syncthreads();
    if (isLast) {
        if (t < Cc) {
            double ts = 0.0, ts2 = 0.0;
            for (int j = 0; j < Bb; j++) { ts += g_ps[which][t][j]; ts2 += g_ps2[which][t][j]; }
            double m = ts / (Bb * Nn);
            double var = ts2 / (Bb * Nn) - m * m;
            (which ? g_mu2 : g_mu1)[t] = (float)m;
            (which ? g_rs2 : g_rs1)[t] = (float)(1.0 / sqrt(var + (double)EPSBN));
        }
        __syncthreads();
        if (t == 0) g_cnt[which] = 0;           // self-reset for next graph replay
    }
}

// ---------------- 7. BN1 apply + FFN + residual ----------------
__global__ void ffn_kernel(const float* __restrict__ W1, const float* __restrict__ W2,
                           const float* __restrict__ g1, const float* __restrict__ b1) {
    int blk = blockIdx.x;
    int b = blk / (Nn / 16);
    int n0 = (blk % (Nn / 16)) * 16;
    __shared__ float Wbuf[128 * 64];
    __shared__ float x1s[64][17];
    __shared__ float hs[128][17];
    int t = threadIdx.x;

    for (int idx = t; idx < 64 * 16; idx += 256) {
        int c = idx >> 4, p = idx & 15;
        float v = g_y[(size_t)b * Cc * Nn + (size_t)c * Nn + n0 + p];
        x1s[c][p] = (v - g_mu1[c]) * g_rs1[c] * g1[c] + b1[c];
    }
    for (int idx = t; idx < 128 * 64; idx += 256) Wbuf[idx] = W1[idx];
    __syncthreads();

    int p = t & 15, obase = t >> 4;
    float hreg[8];
#pragma unroll
    for (int i = 0; i < 8; i++) {
        int o = obase + 16 * i;
        float s = 0.f;
#pragma unroll
        for (int c = 0; c < 64; c++) s = fmaf(Wbuf[o * 64 + c], x1s[c][p], s);
        hreg[i] = (s >= 0.f) ? s : NSLOPE * s;
    }
#pragma unroll
    for (int i = 0; i < 8; i++) hs[obase + 16 * i][p] = hreg[i];
    __syncthreads();
    for (int idx = t; idx < 64 * 128; idx += 256) Wbuf[idx] = W2[idx];
    __syncthreads();

#pragma unroll
    for (int i = 0; i < 4; i++) {
        int c = obase + 16 * i;
        float s = 0.f;
#pragma unroll
        for (int o = 0; o < 128; o++) s = fmaf(Wbuf[c * 128 + o], hs[o][p], s);
        g_y2[(size_t)b * Cc * Nn + (size_t)c * Nn + n0 + p] = x1s[c][p] + s;
    }
}

// ---------------- 9. final BN apply (float4) ----------------
__global__ void apply_kernel(const float* __restrict__ g2, const float* __restrict__ b2,
                             float* __restrict__ out) {
    int i4 = blockIdx.x * blockDim.x + threadIdx.x;      // float4 index
    if (i4 < (Bb * Cc * Nn) / 4) {
        int c = ((i4 * 4) / Nn) & (Cc - 1);
        float4 v = *(const float4*)&g_y2[(size_t)i4 * 4];
        float sc = g_rs2[c] * g2[c], mu = g_mu2[c], bb = b2[c];
        float4 o = make_float4((v.x - mu) * sc + bb, (v.y - mu) * sc + bb,
                               (v.z - mu) * sc + bb, (v.w - mu) * sc + bb);
        *(float4*)&out[(size_t)i4 * 4] = o;
    }
}

// ---------------- launch ----------------
extern "C" void kernel_launch(void* const* d_in, const int* in_sizes, int n_in,
                              void* d_out, int out_size) {
    const float* x  = (const float*)d_in[0];
    const float* Wq = (const float*)d_in[1];
    const float* Wk = (const float*)d_in[2];
    const float* Wv = (const float*)d_in[3];
    const float* W1 = (const float*)d_in[4];
    const float* W2 = (const float*)d_in[5];
    const float* g1 = (const float*)d_in[6];
    const float* b1 = (const float*)d_in[7];
    const float* g2 = (const float*)d_in[8];
    const float* b2 = (const float*)d_in[9];
    float* out = (float*)d_out;

    const int qkv_smem = (64 * 68 + 3 * 64 * 68) * 4;    // 69632 B
    cudaFuncSetAttribute(qkv_kernel, cudaFuncAttributeMaxDynamicSharedMemorySize, qkv_smem);

    qkv_kernel<<<dim3(Nn / 64, Bb), 256, qkv_smem>>>(x, Wq, Wk, Wv);
    dist_kernel<<<dim3(136, 1, Bb), 256>>>(x);
    topk_kernel<<<Bb * Nn, 256>>>();
    attn_kernel<<<Bb * Nn, 256>>>(x);
    statsA_kernel<<<dim3(Cc, Bb), 256>>>(0);
    ffn_kernel<<<Bb * Nn / 16, 256>>>(W1, W2, g1, b1);
    statsA_kernel<<<dim3(Cc, Bb), 256>>>(1);
    apply_kernel<<<(Bb * Cc * Nn / 4 + 255) / 256, 256>>>(g2, b2, out);
}

// round 12
// speedup vs baseline: 1.2486x; 1.1086x over previous
#include <cuda_runtime.h>
#include <math.h>

#define Bb   8
#define Cc   64
#define Nn   2048
#define KNB  32
#define NHEADS 8
#define EPSBN 1e-5f
#define NSLOPE 0.2f

// ---------------- scratch (device globals; no runtime allocation) ----------------
__device__ float g_xx[Bb * Nn];
__device__ float g_D[(size_t)Bb * Nn * Nn];             // 128 MB distance matrix
__device__ int   g_idx[Bb * Nn * KNB];
__device__ float g_Qt[(size_t)Bb * Nn * Cc];            // (B,N,64) point-major
__device__ float g_Kt[(size_t)Bb * Nn * Cc];
__device__ float g_Vt[(size_t)Bb * Nn * Cc];
__device__ float g_y [(size_t)Bb * Cc * Nn];
__device__ float g_y2[(size_t)Bb * Cc * Nn];
__device__ float g_mu1[Cc], g_rs1[Cc], g_mu2[Cc], g_rs2[Cc];
__device__ double g_ps [2][Cc][Bb];
__device__ double g_ps2[2][Cc][Bb];
__device__ int    g_cnt[2];                              // zero-init; self-resetting

// ---------------- packed f32x2 helpers (sm_103a FFMA2 path) ----------------
__device__ __forceinline__ unsigned long long pack2(float x, float y) {
    unsigned long long r;
    asm("mov.b64 %0, {%1, %2};" : "=l"(r) : "f"(x), "f"(y));
    return r;
}
__device__ __forceinline__ unsigned long long ffma2(unsigned long long a,
                                                    unsigned long long b,
                                                    unsigned long long c) {
    unsigned long long d;
    asm("fma.rn.f32x2 %0, %1, %2, %3;" : "=l"(d) : "l"(a), "l"(b), "l"(c));
    return d;
}
__device__ __forceinline__ void unpack2(unsigned long long v, float& lo, float& hi) {
    asm("mov.b64 {%0, %1}, %2;" : "=f"(lo), "=f"(hi) : "l"(v));
}

// ---------------- 1. fused squared norms + Q/K/V projections ----------------
extern __shared__ float dynsmem[];
__global__ void qkv_kernel(const float* __restrict__ x,
                           const float* __restrict__ Wq,
                           const float* __restrict__ Wk,
                           const float* __restrict__ Wv) {
    float (*xs)[68] = (float(*)[68])dynsmem;
    float (*Wt)[68] = (float(*)[68])(dynsmem + 64 * 68);
    int b = blockIdx.y, n0 = blockIdx.x * 64;
    int t = threadIdx.x;
    const float* xb = x + (size_t)b * Cc * Nn;
    for (int idx = t; idx < 4096; idx += 256) {
        int c = idx >> 6, p = idx & 63;
        xs[c][p] = xb[c * Nn + n0 + p];
    }
    const float* Ws[3] = {Wq, Wk, Wv};
#pragma unroll
    for (int m = 0; m < 3; m++)
        for (int idx = t; idx < 4096; idx += 256) {
            int o = idx >> 6, c = idx & 63;
            Wt[m * 64 + c][o] = Ws[m][idx];
        }
    __syncthreads();

    if (t < 64) {                                  // squared norms for these 64 points
        float s = 0.f;
#pragma unroll
        for (int c = 0; c < 64; c++) s = fmaf(xs[c][t], xs[c][t], s);
        g_xx[b * Nn + n0 + t] = s;
    }

    int tx = t & 15, ty = t >> 4;
    float acc[3][4][4] = {};
    for (int c = 0; c < 64; c++) {
        float4 xv4 = *(const float4*)&xs[c][tx * 4];
        float xr[4] = {xv4.x, xv4.y, xv4.z, xv4.w};
#pragma unroll
        for (int m = 0; m < 3; m++) {
            float4 wv4 = *(const float4*)&Wt[m * 64 + c][ty * 4];
            float wr[4] = {wv4.x, wv4.y, wv4.z, wv4.w};
#pragma unroll
            for (int oi = 0; oi < 4; oi++)
#pragma unroll
                for (int pj = 0; pj < 4; pj++)
                    acc[m][oi][pj] = fmaf(wr[oi], xr[pj], acc[m][oi][pj]);
        }
    }
    float* Olist[3] = {g_Qt, g_Kt, g_Vt};
#pragma unroll
    for (int m = 0; m < 3; m++)
#pragma unroll
        for (int pj = 0; pj < 4; pj++) {
            int p = n0 + tx * 4 + pj;
            float4 val = make_float4(acc[m][0][pj], acc[m][1][pj], acc[m][2][pj], acc[m][3][pj]);
            *(float4*)&Olist[m][((size_t)(b * Nn + p)) * 64 + ty * 4] = val;
        }
}

// ---------------- 2. neg squared distance matrix ----------------
__global__ void __launch_bounds__(256, 2) dist_kernel(const float* __restrict__ x) {
    int b = blockIdx.z;
    int p = blockIdx.x, bi = 0;
    while (p >= 16 - bi) { p -= 16 - bi; bi++; }
    int bj = bi + p;
    int i0 = bi * 128, j0 = bj * 128;

    __shared__ float As[32][132];
    __shared__ float Bs[32][132];
    int t = threadIdx.x;
    int tx = t & 15, ty = t >> 4;
    const float* xb = x + (size_t)b * Cc * Nn;

    unsigned long long acc2[4][8];
#pragma unroll
    for (int ip = 0; ip < 4; ip++)
#pragma unroll
        for (int j = 0; j < 8; j++) acc2[ip][j] = 0ull;

    for (int kc = 0; kc < Cc; kc += 32) {
        __syncthreads();
        for (int idx = t; idx < 32 * 128; idx += 256) {
            int c = idx >> 7, q = idx & 127;
            As[c][q] = xb[(kc + c) * Nn + i0 + q];
            Bs[c][q] = xb[(kc + c) * Nn + j0 + q];
        }
        __syncthreads();
#pragma unroll
        for (int c = 0; c < 32; c++) {
            ulonglong2 ap0 = *(const ulonglong2*)&As[c][ty * 8];
            ulonglong2 ap1 = *(const ulonglong2*)&As[c][ty * 8 + 4];
            unsigned long long ap[4] = {ap0.x, ap0.y, ap1.x, ap1.y};
            float4 b0 = *(const float4*)&Bs[c][tx * 8];
            float4 b1 = *(const float4*)&Bs[c][tx * 8 + 4];
            float bv[8] = {b0.x, b0.y, b0.z, b0.w, b1.x, b1.y, b1.z, b1.w};
            unsigned long long bc[8];
#pragma unroll
            for (int j = 0; j < 8; j++) bc[j] = pack2(bv[j], bv[j]);
#pragma unroll
            for (int ip = 0; ip < 4; ip++)
#pragma unroll
                for (int j = 0; j < 8; j++)
                    acc2[ip][j] = ffma2(ap[ip], bc[j], acc2[ip][j]);
        }
    }

    float acc[8][8];
#pragma unroll
    for (int ip = 0; ip < 4; ip++)
#pragma unroll
        for (int j = 0; j < 8; j++)
            unpack2(acc2[ip][j], acc[2 * ip][j], acc[2 * ip + 1][j]);

    float xi[8], xj[8];
#pragma unroll
    for (int ii = 0; ii < 8; ii++) xi[ii] = g_xx[b * Nn + i0 + ty * 8 + ii];
#pragma unroll
    for (int jj = 0; jj < 8; jj++) xj[jj] = g_xx[b * Nn + j0 + tx * 8 + jj];

    float v[8][8];
#pragma unroll
    for (int ii = 0; ii < 8; ii++)
#pragma unroll
        for (int jj = 0; jj < 8; jj++)
            v[ii][jj] = 2.f * acc[ii][jj] - xi[ii] - xj[jj];

#pragma unroll
    for (int ii = 0; ii < 8; ii++) {
        size_t base = ((size_t)b * Nn + i0 + ty * 8 + ii) * Nn + j0 + tx * 8;
        *(float4*)&g_D[base]     = make_float4(v[ii][0], v[ii][1], v[ii][2], v[ii][3]);
        *(float4*)&g_D[base + 4] = make_float4(v[ii][4], v[ii][5], v[ii][6], v[ii][7]);
    }
    if (bi != bj) {
#pragma unroll
        for (int jj = 0; jj < 8; jj++) {
            size_t base = ((size_t)b * Nn + j0 + tx * 8 + jj) * Nn + i0 + ty * 8;
            *(float4*)&g_D[base]     = make_float4(v[0][jj], v[1][jj], v[2][jj], v[3][jj]);
            *(float4*)&g_D[base + 4] = make_float4(v[4][jj], v[5][jj], v[6][jj], v[7][jj]);
        }
    }
}

// ---------------- 3. top-32 per row: 2-level radix + warp micro-select ----------------
__global__ void topk_kernel() {
    int row = blockIdx.x;
    int t = threadIdx.x;                    // 256 threads
    int lane = t & 31, w = t >> 5;
    const float* Drow = g_D + (size_t)row * Nn;

    unsigned int u[8];
    {
        float4 f0 = *(const float4*)(Drow + 8 * t);
        float4 f1 = *(const float4*)(Drow + 8 * t + 4);
        float fv[8] = {f0.x, f0.y, f0.z, f0.w, f1.x, f1.y, f1.z, f1.w};
#pragma unroll
        for (int r = 0; r < 8; r++) {
            unsigned int bits = __float_as_uint(fv[r]);
            u[r] = (bits & 0x80000000u) ? ~bits : (bits | 0x80000000u);
        }
    }

    __shared__ unsigned int hist[256];
    __shared__ unsigned int warpsum[8];
    __shared__ unsigned int sb, sabove;
    __shared__ unsigned long long cand[2048];
    __shared__ int selCnt, candCnt, needSh;

    unsigned int prefix = 0, pmask = 0;
    int need = KNB;

#pragma unroll
    for (int lvl = 0; lvl < 2; lvl++) {
        int shift = 24 - 8 * lvl;
        hist[t] = 0;
        __syncthreads();
#pragma unroll
        for (int r = 0; r < 8; r++)
            if ((u[r] & pmask) == prefix)
                atomicAdd(&hist[(u[r] >> shift) & 255u], 1u);
        __syncthreads();
        unsigned int hv = hist[t];
        unsigned int v = hv;
#pragma unroll
        for (int s = 1; s < 32; s <<= 1) {
            unsigned int o = __shfl_down_sync(0xffffffffu, v, s);
            if (lane + s < 32) v += o;
        }
        if (lane == 0) warpsum[w] = v;
        __syncthreads();
        unsigned int addw = 0;
        for (int j = w + 1; j < 8; j++) addw += warpsum[j];
        unsigned int hs_t = v + addw;
        unsigned int above = hs_t - hv;
        if (hs_t >= (unsigned int)need && above < (unsigned int)need) {
            sb = (unsigned int)t; sabove = above;
        }
        __syncthreads();
        prefix |= sb << shift;
        pmask  |= 0xFFu << shift;
        need   -= (int)sabove;
        __syncthreads();
    }

    if (t == 0) { selCnt = 0; candCnt = 0; needSh = need; }
    __syncthreads();
#pragma unroll
    for (int r = 0; r < 8; r++) {
        int gi = 8 * t + r;
        unsigned int masked = u[r] & pmask;
        if (masked > prefix) {
            int pos = atomicAdd(&selCnt, 1);
            g_idx[row * KNB + pos] = gi;
        } else if (masked == prefix) {
            int pos = atomicAdd(&candCnt, 1);
            cand[pos] = ((unsigned long long)u[r] << 32) | (unsigned int)(2047 - gi);
        }
    }
    __syncthreads();

    if (w == 0) {
        int m = candCnt;
        int base = selCnt;
        int nd = needSh;
        for (int p2 = 0; p2 < nd; p2++) {
            unsigned long long best = 0ull;
            for (int j = lane; j < m; j += 32)
                best = (cand[j] > best) ? cand[j] : best;
#pragma unroll
            for (int s = 16; s; s >>= 1) {
                unsigned long long o = __shfl_xor_sync(0xffffffffu, best, s);
                best = (o > best) ? o : best;
            }
            if (lane == 0)
                g_idx[row * KNB + base + p2] = 2047 - (int)(best & 0xFFFFFFFFull);
            for (int j = lane; j < m; j += 32)
                if (cand[j] == best) cand[j] = 0ull;
        }
    }
}

// ---------------- 5. attention per point: cooperative K/V staging to smem ----------------
__global__ void attn_kernel(const float* __restrict__ x) {
    int row = blockIdx.x;
    int b = row >> 11, n = row & (Nn - 1);
    int t = threadIdx.x;                       // 256 = 8 warps (1 head per warp)
    __shared__ float qv[64], kc[64], vc[64];
    __shared__ int   sid[32];
    __shared__ float Ks[32][68];               // neighbor K rows (stride 68: 4-way max conflict)
    __shared__ float Vs[32][68];               // neighbor V rows
    if (t < 32)                   sid[t]       = g_idx[row * KNB + t];
    else if (t >= 64  && t < 128) qv[t - 64]   = g_Qt[(size_t)row * 64 + (t - 64)];
    if (t >= 128 && t < 192)      kc[t - 128]  = g_Kt[(size_t)row * 64 + (t - 128)];
    else if (t >= 192)            vc[t - 192]  = g_Vt[(size_t)row * 64 + (t - 192)];
    __syncthreads();

    // coalesced staging: idx -> (neighbor r = idx>>4, 16B chunk ch = idx&15)
    // one warp-LDG touches 2 rows x 2 lines = 4 wavefronts (vs 32 for per-head gathers)
#pragma unroll
    for (int it = 0; it < 2; it++) {
        int idx = t + it * 256;                // 0..511
        int r = idx >> 4, ch = (idx & 15) * 4;
        size_t base = ((size_t)(b * Nn + sid[r])) * 64 + ch;
        *(float4*)&Ks[r][ch] = *(const float4*)&g_Kt[base];
        *(float4*)&Vs[r][ch] = *(const float4*)&g_Vt[base];
    }
    __syncthreads();

    int h = t >> 5, kk = t & 31;
    int h8 = h * 8;
    float4 k0 = *(const float4*)&Ks[kk][h8];
    float4 k1 = *(const float4*)&Ks[kk][h8 + 4];
    float e = 0.f;
    e = fmaf(qv[h8 + 0], k0.x - kc[h8 + 0], e);
    e = fmaf(qv[h8 + 1], k0.y - kc[h8 + 1], e);
    e = fmaf(qv[h8 + 2], k0.z - kc[h8 + 2], e);
    e = fmaf(qv[h8 + 3], k0.w - kc[h8 + 3], e);
    e = fmaf(qv[h8 + 4], k1.x - kc[h8 + 4], e);
    e = fmaf(qv[h8 + 5], k1.y - kc[h8 + 5], e);
    e = fmaf(qv[h8 + 6], k1.z - kc[h8 + 6], e);
    e = fmaf(qv[h8 + 7], k1.w - kc[h8 + 7], e);
    e *= 0.3535533905932738f;                 // 1/sqrt(8)

    float m = e;
#pragma unroll
    for (int s = 16; s; s >>= 1) m = fmaxf(m, __shfl_xor_sync(0xffffffffu, m, s));
    float ex = expf(e - m);
    float ssum = ex;
#pragma unroll
    for (int s = 16; s; s >>= 1) ssum += __shfl_xor_sync(0xffffffffu, ssum, s);
    float a = ex / ssum;

    float4 v0 = *(const float4*)&Vs[kk][h8];
    float4 v1 = *(const float4*)&Vs[kk][h8 + 4];
    float vv[8] = {v0.x - vc[h8 + 0], v0.y - vc[h8 + 1], v0.z - vc[h8 + 2], v0.w - vc[h8 + 3],
                   v1.x - vc[h8 + 4], v1.y - vc[h8 + 5], v1.z - vc[h8 + 6], v1.w - vc[h8 + 7]};
#pragma unroll
    for (int d = 0; d < 8; d++) {
        float pd = a * vv[d];
#pragma unroll
        for (int s = 16; s; s >>= 1) pd += __shfl_xor_sync(0xffffffffu, pd, s);
        if (kk == d) {
            int c = h8 + d;
            size_t gi = (size_t)b * Cc * Nn + (size_t)c * Nn + n;
            g_y[gi] = x[gi] + pd;
        }
    }
}

// ---------------- 6/8. BN stats, single kernel with last-block finalize ----------------
__global__ void statsA_kernel(int which) {
    const float* in = which ? g_y2 : g_y;
    int c = blockIdx.x, b = blockIdx.y, t = threadIdx.x;
    int lane = t & 31, w = t >> 5;
    const float* p = in + (size_t)b * Cc * Nn + (size_t)c * Nn;
    double s = 0.0, s2 = 0.0;
    for (int n = t; n < Nn; n += 256) { float v = p[n]; s += v; s2 += (double)v * v; }
#pragma unroll
    for (int o = 16; o; o >>= 1) {
        s  += __shfl_down_sync(0xffffffffu, s, o);
        s2 += __shfl_down_sync(0xffffffffu, s2, o);
    }
    __shared__ double ws[8], ws2[8];
    __shared__ int isLast;
    if (lane == 0) { ws[w] = s; ws2[w] = s2; }
    __syncthreads();
    if (t == 0) {
        double ts = 0.0, ts2 = 0.0;
        for (int j = 0; j < 8; j++) { ts += ws[j]; ts2 += ws2[j]; }
        g_ps[which][c][b] = ts;
        g_ps2[which][c][b] = ts2;
        __threadfence();
        int v = atomicAdd(&g_cnt[which], 1);
        isLast = (v == Cc * Bb - 1);
    }
    __syncthreads();
    if (isLast) {
        if (t < Cc) {
            double ts = 0.0, ts2 = 0.0;
            for (int j = 0; j < Bb; j++) { ts += g_ps[which][t][j]; ts2 += g_ps2[which][t][j]; }
            double m = ts / (Bb * Nn);
            double var = ts2 / (Bb * Nn) - m * m;
            (which ? g_mu2 : g_mu1)[t] = (float)m;
            (which ? g_rs2 : g_rs1)[t] = (float)(1.0 / sqrt(var + (double)EPSBN));
        }
        __syncthreads();
        if (t == 0) g_cnt[which] = 0;           // self-reset for next graph replay
    }
}

// ---------------- 7. BN1 apply + FFN + residual ----------------
__global__ void ffn_kernel(const float* __restrict__ W1, const float* __restrict__ W2,
                           const float* __restrict__ g1, const float* __restrict__ b1) {
    int blk = blockIdx.x;
    int b = blk / (Nn / 16);
    int n0 = (blk % (Nn / 16)) * 16;
    __shared__ float Wbuf[128 * 64];
    __shared__ float x1s[64][17];
    __shared__ float hs[128][17];
    int t = threadIdx.x;

    for (int idx = t; idx < 64 * 16; idx += 256) {
        int c = idx >> 4, p = idx & 15;
        float v = g_y[(size_t)b * Cc * Nn + (size_t)c * Nn + n0 + p];
        x1s[c][p] = (v - g_mu1[c]) * g_rs1[c] * g1[c] + b1[c];
    }
    for (int idx = t; idx < 128 * 64; idx += 256) Wbuf[idx] = W1[idx];
    __syncthreads();

    int p = t & 15, obase = t >> 4;
    float hreg[8];
#pragma unroll
    for (int i = 0; i < 8; i++) {
        int o = obase + 16 * i;
        float s = 0.f;
#pragma unroll
        for (int c = 0; c < 64; c++) s = fmaf(Wbuf[o * 64 + c], x1s[c][p], s);
        hreg[i] = (s >= 0.f) ? s : NSLOPE * s;
    }
#pragma unroll
    for (int i = 0; i < 8; i++) hs[obase + 16 * i][p] = hreg[i];
    __syncthreads();
    for (int idx = t; idx < 64 * 128; idx += 256) Wbuf[idx] = W2[idx];
    __syncthreads();

#pragma unroll
    for (int i = 0; i < 4; i++) {
        int c = obase + 16 * i;
        float s = 0.f;
#pragma unroll
        for (int o = 0; o < 128; o++) s = fmaf(Wbuf[c * 128 + o], hs[o][p], s);
        g_y2[(size_t)b * Cc * Nn + (size_t)c * Nn + n0 + p] = x1s[c][p] + s;
    }
}

// ---------------- 9. final BN apply (float4) ----------------
__global__ void apply_kernel(const float* __restrict__ g2, const float* __restrict__ b2,
                             float* __restrict__ out) {
    int i4 = blockIdx.x * blockDim.x + threadIdx.x;      // float4 index
    if (i4 < (Bb * Cc * Nn) / 4) {
        int c = ((i4 * 4) / Nn) & (Cc - 1);
        float4 v = *(const float4*)&g_y2[(size_t)i4 * 4];
        float sc = g_rs2[c] * g2[c], mu = g_mu2[c], bb = b2[c];
        float4 o = make_float4((v.x - mu) * sc + bb, (v.y - mu) * sc + bb,
                               (v.z - mu) * sc + bb, (v.w - mu) * sc + bb);
        *(float4*)&out[(size_t)i4 * 4] = o;
    }
}

// ---------------- launch ----------------
extern "C" void kernel_launch(void* const* d_in, const int* in_sizes, int n_in,
                              void* d_out, int out_size) {
    const float* x  = (const float*)d_in[0];
    const float* Wq = (const float*)d_in[1];
    const float* Wk = (const float*)d_in[2];
    const float* Wv = (const float*)d_in[3];
    const float* W1 = (const float*)d_in[4];
    const float* W2 = (const float*)d_in[5];
    const float* g1 = (const float*)d_in[6];
    const float* b1 = (const float*)d_in[7];
    const float* g2 = (const float*)d_in[8];
    const float* b2 = (const float*)d_in[9];
    float* out = (float*)d_out;

    const int qkv_smem = (64 * 68 + 3 * 64 * 68) * 4;    // 69632 B
    cudaFuncSetAttribute(qkv_kernel, cudaFuncAttributeMaxDynamicSharedMemorySize, qkv_smem);

    qkv_kernel<<<dim3(Nn / 64, Bb), 256, qkv_smem>>>(x, Wq, Wk, Wv);
    dist_kernel<<<dim3(136, 1, Bb), 256>>>(x);
    topk_kernel<<<Bb * Nn, 256>>>();
    attn_kernel<<<Bb * Nn, 256>>>(x);
    statsA_kernel<<<dim3(Cc, Bb), 256>>>(0);
    ffn_kernel<<<Bb * Nn / 16, 256>>>(W1, W2, g1, b1);
    statsA_kernel<<<dim3(Cc, Bb), 256>>>(1);
    apply_kernel<<<(Bb * Cc * Nn / 4 + 255) / 256, 256>>>(g2, b2, out);
}